// round 2
// baseline (speedup 1.0000x reference)
#include <cuda_runtime.h>
#include <cuda_bf16.h>
#include <cstdint>
#include <cstddef>

#define BB   256   // batch
#define LL   512   // seq len
#define EE   256   // encoder dim
#define HH   128   // hidden
#define G4   512   // 4*H
#define TB   8     // batch tile per recurrent cluster
#define NBT  32    // 256/TB

// ---------------------------------------------------------------------------
// Device scratch (allocation-free rule: __device__ globals)
// ---------------------------------------------------------------------------
__device__ float g_gx[(size_t)2 * LL * BB * G4];   // 512 MB gate pre-activations
__device__ float g_yp[(size_t)4 * BB * LL];        // partial y: [cell*2+rank][b][t]

// ---------------------------------------------------------------------------
// f32x2 packed FMA helpers (sm_100+; 2x FFMA throughput, PTX-only form)
// ---------------------------------------------------------------------------
static __device__ __forceinline__ unsigned long long pack2(float x, float y) {
    unsigned long long r;
    asm("mov.b64 %0, {%1, %2};" : "=l"(r) : "f"(x), "f"(y));
    return r;
}
static __device__ __forceinline__ void fma2(unsigned long long& d,
                                            unsigned long long a,
                                            unsigned long long b) {
    asm("fma.rn.f32x2 %0, %1, %2, %0;" : "+l"(d) : "l"(a), "l"(b));
}
static __device__ __forceinline__ float2 unpack2(unsigned long long v) {
    float2 f;
    asm("mov.b64 {%0, %1}, %2;" : "=f"(f.x), "=f"(f.y) : "l"(v));
    return f;
}
static __device__ __forceinline__ uint32_t smem_u32(const void* p) {
    uint32_t a;
    asm("{ .reg .u64 t; cvta.to.shared.u64 t, %1; cvt.u32.u64 %0, t; }"
        : "=r"(a) : "l"(p));
    return a;
}
static __device__ __forceinline__ void st_remote_f32(uint32_t laddr, uint32_t peer, float v) {
    asm volatile(
        "{ .reg .b32 ra; mapa.shared::cluster.u32 ra, %0, %1; "
        "st.shared::cluster.f32 [ra], %2; }"
        :: "r"(laddr), "r"(peer), "f"(v) : "memory");
}
static __device__ __forceinline__ float sigm(float x) {
    return 1.0f / (1.0f + __expf(-x));
}

// ---------------------------------------------------------------------------
// Phase 1: Gx[cell][t][b][n] = X[b][t][:] . W_ih[n][:] + b_ih[n] + b_hh[n]
// M = L*B rows (r = t*256 + b), N = 512, K = 256. 128x128x8 tiles, 8x8/thread.
// ---------------------------------------------------------------------------
#define BM 128
#define BN 128
#define BKC 8

__global__ __launch_bounds__(256, 2) void k_input_gemm(
    const float* __restrict__ Xh, const float* __restrict__ Xf,
    const float* __restrict__ Wih_h, const float* __restrict__ Wih_f,
    const float* __restrict__ bih_h, const float* __restrict__ bhh_h,
    const float* __restrict__ bih_f, const float* __restrict__ bhh_f)
{
    const int cell = blockIdx.z;
    const float* X  = cell ? Xf : Xh;
    const float* W  = cell ? Wih_f : Wih_h;
    const float* bi = cell ? bih_f : bih_h;
    const float* bh = cell ? bhh_f : bhh_h;

    const int n0 = blockIdx.x * BN;
    const int r0 = blockIdx.y * BM;

    __shared__ float As[BKC][BM + 4];
    __shared__ float Bs[BKC][BN + 4];

    const int tid = threadIdx.x;
    const int lr = tid >> 1;            // 0..127
    const int lk = (tid & 1) * 4;       // 0 or 4

    const int rA = r0 + lr;
    const int tA = rA >> 8;
    const int bA = rA & 255;
    const float* Ap = X + ((size_t)bA * LL + tA) * EE + lk;
    const float* Bp = W + (size_t)(n0 + lr) * EE + lk;

    const int tx = tid & 15;
    const int ty = tid >> 4;

    unsigned long long acc[8][4];
#pragma unroll
    for (int i = 0; i < 8; i++)
#pragma unroll
        for (int j = 0; j < 4; j++) acc[i][j] = 0ull;

    for (int k0 = 0; k0 < EE; k0 += BKC) {
        float4 av = *reinterpret_cast<const float4*>(Ap + k0);
        float4 bv = *reinterpret_cast<const float4*>(Bp + k0);
        As[lk + 0][lr] = av.x; As[lk + 1][lr] = av.y;
        As[lk + 2][lr] = av.z; As[lk + 3][lr] = av.w;
        Bs[lk + 0][lr] = bv.x; Bs[lk + 1][lr] = bv.y;
        Bs[lk + 2][lr] = bv.z; Bs[lk + 3][lr] = bv.w;
        __syncthreads();
#pragma unroll
        for (int kk = 0; kk < BKC; kk++) {
            float4 a0 = *reinterpret_cast<const float4*>(&As[kk][ty * 8]);
            float4 a1 = *reinterpret_cast<const float4*>(&As[kk][ty * 8 + 4]);
            const unsigned long long* bp2 =
                reinterpret_cast<const unsigned long long*>(&Bs[kk][tx * 8]);
            unsigned long long b0 = bp2[0], b1 = bp2[1], b2 = bp2[2], b3 = bp2[3];
            float aa[8] = {a0.x, a0.y, a0.z, a0.w, a1.x, a1.y, a1.z, a1.w};
#pragma unroll
            for (int i = 0; i < 8; i++) {
                unsigned long long ap = pack2(aa[i], aa[i]);
                fma2(acc[i][0], ap, b0);
                fma2(acc[i][1], ap, b1);
                fma2(acc[i][2], ap, b2);
                fma2(acc[i][3], ap, b3);
            }
        }
        __syncthreads();
    }

    float bias[8];
#pragma unroll
    for (int j = 0; j < 8; j++)
        bias[j] = bi[n0 + tx * 8 + j] + bh[n0 + tx * 8 + j];

#pragma unroll
    for (int i = 0; i < 8; i++) {
        int r = r0 + ty * 8 + i;
        int t = r >> 8, b = r & 255;
        float* op = g_gx + (((size_t)cell * LL + t) * BB + b) * (size_t)G4
                         + n0 + tx * 8;
        float2 p0 = unpack2(acc[i][0]);
        float2 p1 = unpack2(acc[i][1]);
        float2 p2 = unpack2(acc[i][2]);
        float2 p3 = unpack2(acc[i][3]);
        float4 o0, o1;
        o0.x = p0.x + bias[0]; o0.y = p0.y + bias[1];
        o0.z = p1.x + bias[2]; o0.w = p1.y + bias[3];
        o1.x = p2.x + bias[4]; o1.y = p2.y + bias[5];
        o1.z = p3.x + bias[6]; o1.w = p3.y + bias[7];
        reinterpret_cast<float4*>(op)[0] = o0;
        reinterpret_cast<float4*>(op)[1] = o1;
    }
}

// ---------------------------------------------------------------------------
// Phase 2: recurrent LSTM. Cluster of 2 CTAs per (cell, batch-tile) chain.
// Rank r owns gate rows {g*128 + r*64 + jj : g<4, jj<64} with weights in regs
// (1 row / thread, 256 threads, 64 f32x2 pairs each). smem holds only
// double-buffered full h, gates staging, c. One cluster barrier per step.
// ---------------------------------------------------------------------------
__global__ __launch_bounds__(256, 1) __cluster_dims__(2, 1, 1)
void k_recurrent(const float* __restrict__ Whh_h,
                 const float* __restrict__ Whh_f,
                 const float* __restrict__ Wffn)
{
    __shared__ float h_s[2][TB][HH];       // 8 KB, double-buffered full hidden
    __shared__ float gates_s[256][TB];     // 8 KB, [rr][b]
    __shared__ float c_s[TB][64];          // 2 KB, this rank's c half
    __shared__ float y_ws[TB][2];          // warp partial y

    const int tid = threadIdx.x;
    uint32_t rank;
    asm("mov.u32 %0, %%cluster_ctarank;" : "=r"(rank));
    const int q    = blockIdx.x >> 1;      // cluster id
    const int cell = q >> 5;               // 0..1
    const int bt   = q & 31;               // batch tile
    const int b0   = bt * TB;

    const float* W = cell ? Whh_f : Whh_h;

    const int rr = tid;                    // local gate row 0..255
    const int g  = rr >> 6;
    const int jj = rr & 63;
    const int n  = g * HH + (int)rank * 64 + jj;  // global gate row

    // Load this thread's W_hh row into registers as 64 f32x2 pairs.
    unsigned long long w2[64];
    {
        const float2* wrow = reinterpret_cast<const float2*>(W + (size_t)n * HH);
#pragma unroll
        for (int i = 0; i < 64; i++) {
            float2 v = wrow[i];
            w2[i] = pack2(v.x, v.y);
        }
    }

    // Update-phase mapping: thread -> (jju, batches bA and bA+4)
    const int lane = tid & 31;
    const int wrp  = tid >> 5;
    const int jju  = tid & 63;
    const int bA   = tid >> 6;             // 0..3
    const float wf = Wffn[cell * HH + (int)rank * 64 + jju];
    const int jglob = (int)rank * 64 + jju;

    // Zero-init state
    for (int i = tid; i < 2 * TB * HH; i += 256) (&h_s[0][0][0])[i] = 0.0f;
    for (int i = tid; i < TB * 64;     i += 256) (&c_s[0][0])[i]     = 0.0f;
    __syncthreads();
    asm volatile("barrier.cluster.arrive.aligned;" ::: "memory");
    asm volatile("barrier.cluster.wait.aligned;"   ::: "memory");

    // Gx addressing: addr(t,b) = cbase + (t*BB + b0+b)*G4
    const size_t cbase = (size_t)cell * LL * BB * G4 + (size_t)n;
    float gx[TB];
#pragma unroll
    for (int b = 0; b < TB; b++)
        gx[b] = g_gx[cbase + (size_t)(b0 + b) * G4];

    int buf = 0;
    for (int t = 0; t < LL; t++) {
        // Software-prefetch next step's Gx (hidden under this step's FMAs)
        float gxn[TB];
        {
            const float* gp = g_gx + cbase + ((size_t)(t + 1) * BB + b0) * G4;
#pragma unroll
            for (int b = 0; b < TB; b++)
                gxn[b] = (t + 1 < LL) ? gp[(size_t)b * G4] : 0.0f;
        }

        // Gate matvec: gates_s[rr][b] = gx[b] + h[b] . w_row
#pragma unroll
        for (int b = 0; b < TB; b++) {
            const unsigned long long* hp =
                reinterpret_cast<const unsigned long long*>(&h_s[buf][b][0]);
            unsigned long long a0 = 0ull, a1 = 0ull;
#pragma unroll
            for (int i = 0; i < 64; i += 2) {
                fma2(a0, hp[i],     w2[i]);
                fma2(a1, hp[i + 1], w2[i + 1]);
            }
            float2 s0 = unpack2(a0);
            float2 s1 = unpack2(a1);
            gates_s[rr][b] = gx[b] + ((s0.x + s0.y) + (s1.x + s1.y));
        }
        __syncthreads();

        // Pointwise update for (jju, bA) and (jju, bA+4)
        const int nb = buf ^ 1;
#pragma unroll
        for (int u = 0; u < 2; u++) {
            const int b = bA + 4 * u;
            float ig = sigm(gates_s[jju][b]);
            float fg = sigm(gates_s[64 + jju][b]);
            float gg = tanhf(gates_s[128 + jju][b]);
            float og = sigm(gates_s[192 + jju][b]);
            float c  = fg * c_s[b][jju] + ig * gg;
            c_s[b][jju] = c;
            float hv = og * tanhf(c);
            h_s[nb][b][jglob] = hv;
            st_remote_f32(smem_u32(&h_s[nb][b][jglob]), rank ^ 1u, hv);

            float y = hv * wf;
#pragma unroll
            for (int off = 16; off; off >>= 1)
                y += __shfl_xor_sync(0xffffffffu, y, off);
            if (lane == 0) y_ws[b][wrp & 1] = y;
        }
        __syncthreads();

        if (tid < TB) {
            float y = y_ws[tid][0] + y_ws[tid][1];
            g_yp[((size_t)(cell * 2 + (int)rank) * BB + (b0 + tid)) * LL + t] = y;
        }

#pragma unroll
        for (int b = 0; b < TB; b++) gx[b] = gxn[b];
        buf ^= 1;

        // Publish h halves cluster-wide; also the per-step CTA barrier.
        asm volatile("barrier.cluster.arrive.aligned;" ::: "memory");
        asm volatile("barrier.cluster.wait.aligned;"   ::: "memory");
    }
}

// ---------------------------------------------------------------------------
// Phase 3: out[b][t] = sum of 4 partials + b_ffn
// ---------------------------------------------------------------------------
__global__ void k_finalize(float* __restrict__ out, const float* __restrict__ bffn) {
    int i = blockIdx.x * 256 + threadIdx.x;   // i = b*LL + t
    if (i < BB * LL) {
        const size_t s = (size_t)BB * LL;
        float y = bffn[0] + g_yp[i] + g_yp[s + i] + g_yp[2 * s + i] + g_yp[3 * s + i];
        out[i] = y;
    }
}

// ---------------------------------------------------------------------------
extern "C" void kernel_launch(void* const* d_in, const int* in_sizes, int n_in,
                              void* d_out, int out_size) {
    const float* hist  = (const float*)d_in[0];
    const float* fut   = (const float*)d_in[1];
    const float* Wih_h = (const float*)d_in[2];
    const float* Whh_h = (const float*)d_in[3];
    const float* bih_h = (const float*)d_in[4];
    const float* bhh_h = (const float*)d_in[5];
    const float* Wih_f = (const float*)d_in[6];
    const float* Whh_f = (const float*)d_in[7];
    const float* bih_f = (const float*)d_in[8];
    const float* bhh_f = (const float*)d_in[9];
    const float* Wffn  = (const float*)d_in[10];
    const float* bffn  = (const float*)d_in[11];
    float* out = (float*)d_out;

    dim3 g1(G4 / BN, (LL * BB) / BM, 2);   // (4, 1024, 2)
    k_input_gemm<<<g1, 256>>>(hist, fut, Wih_h, Wih_f, bih_h, bhh_h, bih_f, bhh_f);

    k_recurrent<<<128, 256>>>(Whh_h, Whh_f, Wffn);

    k_finalize<<<(BB * LL + 255) / 256, 256>>>(out, bffn);
}

// round 4
// speedup vs baseline: 1.4064x; 1.4064x over previous
#include <cuda_runtime.h>
#include <cuda_bf16.h>
#include <cstdint>
#include <cstddef>

#define BB   256
#define LL   512
#define EE   256
#define HH   128
#define G4   512
#define TB   8
#define MROWS 131072          // L*B rows per cell
#define KTOT  768             // 3 * 256 (hi|hi|lo split-K)
#define NCH   24              // 768 / 32

// ---------------------------------------------------------------------------
// Device scratch
// ---------------------------------------------------------------------------
__device__ float g_gx[(size_t)2 * LL * BB * G4];            // 512 MB gates
__device__ __nv_bfloat16 g_ap[(size_t)2 * MROWS * KTOT];    // 402 MB A' (hi|hi|lo)
__device__ __nv_bfloat16 g_wp[(size_t)2 * G4 * KTOT];       // 1.5 MB W' (hi|lo|hi)
__device__ float g_yp[(size_t)4 * BB * LL];                 // y partials

// ---------------------------------------------------------------------------
// Helpers
// ---------------------------------------------------------------------------
static __device__ __forceinline__ unsigned long long pack2(float x, float y) {
    unsigned long long r;
    asm("mov.b64 %0, {%1, %2};" : "=l"(r) : "f"(x), "f"(y));
    return r;
}
static __device__ __forceinline__ void fma2(unsigned long long& d,
                                            unsigned long long a,
                                            unsigned long long b) {
    asm("fma.rn.f32x2 %0, %1, %2, %0;" : "+l"(d) : "l"(a), "l"(b));
}
static __device__ __forceinline__ float2 unpack2(unsigned long long v) {
    float2 f;
    asm("mov.b64 {%0, %1}, %2;" : "=f"(f.x), "=f"(f.y) : "l"(v));
    return f;
}
static __device__ __forceinline__ uint32_t smem_u32(const void* p) {
    uint32_t a;
    asm("{ .reg .u64 t; cvta.to.shared.u64 t, %1; cvt.u32.u64 %0, t; }"
        : "=r"(a) : "l"(p));
    return a;
}
static __device__ __forceinline__ void st_remote_f32(uint32_t laddr, uint32_t peer, float v) {
    asm volatile(
        "{ .reg .b32 ra; mapa.shared::cluster.u32 ra, %0, %1; "
        "st.shared::cluster.f32 [ra], %2; }"
        :: "r"(laddr), "r"(peer), "f"(v) : "memory");
}
// fast activations (ex2/rcp approx)
static __device__ __forceinline__ float sigm(float x) {
    float t;
    asm("mul.f32 %0, %1, 0fBFB8AA3B;" : "=f"(t) : "f"(x));   // -x*log2(e)
    asm("ex2.approx.f32 %0, %0;" : "+f"(t));
    float r = t + 1.0f;
    asm("rcp.approx.f32 %0, %0;" : "+f"(r));
    return r;
}
static __device__ __forceinline__ float tanha(float x) {
    x = fminf(fmaxf(x, -9.0f), 9.0f);
    float t;
    asm("mul.f32 %0, %1, 0f4038AA3B;" : "=f"(t) : "f"(x));   // 2x*log2(e)
    asm("ex2.approx.f32 %0, %0;" : "+f"(t));                  // e^{2x}
    float den = t + 1.0f;
    asm("rcp.approx.f32 %0, %0;" : "+f"(den));
    return (t - 1.0f) * den;
}
// cp.async
static __device__ __forceinline__ void cp16(uint32_t dst, const void* src) {
    asm volatile("cp.async.cg.shared.global [%0], [%1], 16;"
                 :: "r"(dst), "l"(src) : "memory");
}
static __device__ __forceinline__ void cp_commit() {
    asm volatile("cp.async.commit_group;" ::: "memory");
}
template <int N>
static __device__ __forceinline__ void cp_wait() {
    asm volatile("cp.async.wait_group %0;" :: "n"(N) : "memory");
}
// ldmatrix x4 (b16)
static __device__ __forceinline__ void ldx4(uint32_t* r, uint32_t addr) {
    asm volatile("ldmatrix.sync.aligned.m8n8.x4.shared.b16 {%0,%1,%2,%3}, [%4];"
                 : "=r"(r[0]), "=r"(r[1]), "=r"(r[2]), "=r"(r[3]) : "r"(addr));
}
// bf16 HMMA m16n8k16, fp32 accum
static __device__ __forceinline__ void mma16816(float* c, const uint32_t* a,
                                                uint32_t b0, uint32_t b1) {
    asm volatile(
        "mma.sync.aligned.m16n8k16.row.col.f32.bf16.bf16.f32 "
        "{%0,%1,%2,%3}, {%4,%5,%6,%7}, {%8,%9}, {%0,%1,%2,%3};"
        : "+f"(c[0]), "+f"(c[1]), "+f"(c[2]), "+f"(c[3])
        : "r"(a[0]), "r"(a[1]), "r"(a[2]), "r"(a[3]), "r"(b0), "r"(b1));
}
static __device__ __forceinline__ uint32_t bfpack(__nv_bfloat16 a, __nv_bfloat16 b) {
    return (uint32_t)__bfloat16_as_ushort(a) | ((uint32_t)__bfloat16_as_ushort(b) << 16);
}

// ---------------------------------------------------------------------------
// Convert X -> A' = [hi | hi | lo]  (bf16, row r = t*256+b, K'=768)
// ---------------------------------------------------------------------------
__global__ __launch_bounds__(256) void k_convert(const float* __restrict__ Xh,
                                                 const float* __restrict__ Xf) {
    size_t i = (size_t)blockIdx.x * 256 + threadIdx.x;
    int e8 = (int)(i & 31);
    size_t rr = i >> 5;                                  // cell*MROWS + r
    int cell = (int)(rr >> 17);
    int r = (int)(rr & (MROWS - 1));
    int t = r >> 8, b = r & 255;
    const float* X = cell ? Xf : Xh;
    const float4* src = reinterpret_cast<const float4*>(X + ((size_t)b * LL + t) * EE + e8 * 8);
    float4 v0 = src[0], v1 = src[1];
    float x[8] = {v0.x, v0.y, v0.z, v0.w, v1.x, v1.y, v1.z, v1.w};
    __nv_bfloat16 hi[8], lo[8];
#pragma unroll
    for (int j = 0; j < 8; j++) {
        hi[j] = __float2bfloat16(x[j]);
        lo[j] = __float2bfloat16(x[j] - __bfloat162float(hi[j]));
    }
    uint4 ph, pl;
    ph.x = bfpack(hi[0], hi[1]); ph.y = bfpack(hi[2], hi[3]);
    ph.z = bfpack(hi[4], hi[5]); ph.w = bfpack(hi[6], hi[7]);
    pl.x = bfpack(lo[0], lo[1]); pl.y = bfpack(lo[2], lo[3]);
    pl.z = bfpack(lo[4], lo[5]); pl.w = bfpack(lo[6], lo[7]);
    __nv_bfloat16* dst = g_ap + rr * KTOT + e8 * 8;
    *reinterpret_cast<uint4*>(dst)       = ph;
    *reinterpret_cast<uint4*>(dst + 256) = ph;
    *reinterpret_cast<uint4*>(dst + 512) = pl;
}

// W' = [hi | lo | hi]
__global__ __launch_bounds__(256) void k_convert_w(const float* __restrict__ Wh,
                                                   const float* __restrict__ Wf) {
    int i = blockIdx.x * 256 + threadIdx.x;
    int e8 = i & 31;
    int nn = i >> 5;                                     // cell*512 + n
    int cell = nn >> 9;
    int n = nn & 511;
    const float* W = cell ? Wf : Wh;
    const float4* src = reinterpret_cast<const float4*>(W + (size_t)n * EE + e8 * 8);
    float4 v0 = src[0], v1 = src[1];
    float x[8] = {v0.x, v0.y, v0.z, v0.w, v1.x, v1.y, v1.z, v1.w};
    __nv_bfloat16 hi[8], lo[8];
#pragma unroll
    for (int j = 0; j < 8; j++) {
        hi[j] = __float2bfloat16(x[j]);
        lo[j] = __float2bfloat16(x[j] - __bfloat162float(hi[j]));
    }
    uint4 ph, pl;
    ph.x = bfpack(hi[0], hi[1]); ph.y = bfpack(hi[2], hi[3]);
    ph.z = bfpack(hi[4], hi[5]); ph.w = bfpack(hi[6], hi[7]);
    pl.x = bfpack(lo[0], lo[1]); pl.y = bfpack(lo[2], lo[3]);
    pl.z = bfpack(lo[4], lo[5]); pl.w = bfpack(lo[6], lo[7]);
    __nv_bfloat16* dst = g_wp + (size_t)nn * KTOT + e8 * 8;
    *reinterpret_cast<uint4*>(dst)       = ph;
    *reinterpret_cast<uint4*>(dst + 256) = pl;   // pairs with A hi
    *reinterpret_cast<uint4*>(dst + 512) = ph;   // pairs with A lo
}

// ---------------------------------------------------------------------------
// Phase 1 GEMM via mma.sync bf16: C[m,n] = sum_k A'[m,k] W'[n,k] (+bias).
// CTA 128x128, 8 warps (4M x 2N), warp 32x64, K-chunk 32, cp.async dbuf.
// smem row stride 40 bf16 (80B): conflict-free ldmatrix, 16B-aligned.
// ---------------------------------------------------------------------------
#define ASTRIDE 40

__global__ __launch_bounds__(256, 2) void k_mma_gemm(
    const float* __restrict__ bih_h, const float* __restrict__ bhh_h,
    const float* __restrict__ bih_f, const float* __restrict__ bhh_f)
{
    __shared__ __align__(16) __nv_bfloat16 As[2][128 * ASTRIDE];
    __shared__ __align__(16) __nv_bfloat16 Bs[2][128 * ASTRIDE];
    __shared__ float bias_s[128];

    const int tid  = threadIdx.x;
    const int wid  = tid >> 5;
    const int lane = tid & 31;
    const int n0 = blockIdx.x * 128;
    const int m0 = blockIdx.y * 128;
    const int cell = m0 >> 17;

    if (tid < 128) {
        const float* bi = cell ? bih_f : bih_h;
        const float* bh = cell ? bhh_f : bhh_h;
        bias_s[tid] = bi[n0 + tid] + bh[n0 + tid];
    }

    const __nv_bfloat16* Asrc = g_ap + (size_t)m0 * KTOT;
    const __nv_bfloat16* Bsrc = g_wp + ((size_t)cell * G4 + n0) * KTOT;

    const uint32_t sa = smem_u32(&As[0][0]);
    const uint32_t sb = smem_u32(&Bs[0][0]);
    const uint32_t bufstride = 128 * ASTRIDE * 2;   // bytes per buffer

    // loader: thread -> row = tid>>1, two 16B pieces at u = (tid&1)*2
    const int lrow = tid >> 1;
    const int lu   = (tid & 1) * 2;
    const uint32_t a_dst0 = sa + lrow * (ASTRIDE * 2) + lu * 16;
    const uint32_t b_dst0 = sb + lrow * (ASTRIDE * 2) + lu * 16;
    const __nv_bfloat16* a_src0 = Asrc + (size_t)lrow * KTOT + lu * 8;
    const __nv_bfloat16* b_src0 = Bsrc + (size_t)lrow * KTOT + lu * 8;

#define LOAD_CHUNK(c)                                                      \
    do {                                                                   \
        int _buf = (c) & 1;                                                \
        int _k0 = (c) * 32;                                                \
        cp16(a_dst0 + _buf * bufstride,      a_src0 + _k0);                \
        cp16(a_dst0 + _buf * bufstride + 16, a_src0 + _k0 + 8);            \
        cp16(b_dst0 + _buf * bufstride,      b_src0 + _k0);                \
        cp16(b_dst0 + _buf * bufstride + 16, b_src0 + _k0 + 8);            \
        cp_commit();                                                       \
    } while (0)

    // warp tiling
    const int warp_m = wid & 3;        // 4 tiles of 32 rows
    const int warp_n = wid >> 2;       // 2 tiles of 64 cols

    // ldmatrix lane addresses (k-independent parts)
    // A x4: row = warp_m*32 + im*16 + lane%16 ; kcol = (lane/16)*8
    uint32_t a_addr[2];
#pragma unroll
    for (int im = 0; im < 2; im++) {
        int row = warp_m * 32 + im * 16 + (lane & 15);
        a_addr[im] = sa + row * (ASTRIDE * 2) + (lane >> 4) * 16;
    }
    // B x4: row = warp_n*64 + ip*16 + (lane/16)*8 + (lane&7) ; kcol = ((lane>>3)&1)*8
    uint32_t b_addr[4];
#pragma unroll
    for (int ip = 0; ip < 4; ip++) {
        int row = warp_n * 64 + ip * 16 + (lane >> 4) * 8 + (lane & 7);
        b_addr[ip] = sb + row * (ASTRIDE * 2) + ((lane >> 3) & 1) * 16;
    }

    float acc[2][8][4];
#pragma unroll
    for (int im = 0; im < 2; im++)
#pragma unroll
        for (int in = 0; in < 8; in++)
#pragma unroll
            for (int q = 0; q < 4; q++) acc[im][in][q] = 0.0f;

    LOAD_CHUNK(0);

    for (int c = 0; c < NCH; ++c) {
        if (c + 1 < NCH) { LOAD_CHUNK(c + 1); cp_wait<1>(); }
        else             { cp_wait<0>(); }
        __syncthreads();

        const uint32_t boff = (uint32_t)(c & 1) * bufstride;
#pragma unroll
        for (int ks = 0; ks < 2; ks++) {
            const uint32_t kb = boff + ks * 32;        // 16 bf16 = 32B
            uint32_t afr[2][4];
            ldx4(afr[0], a_addr[0] + kb);
            ldx4(afr[1], a_addr[1] + kb);
            uint32_t bfr[16];
            ldx4(bfr + 0,  b_addr[0] + kb);
            ldx4(bfr + 4,  b_addr[1] + kb);
            ldx4(bfr + 8,  b_addr[2] + kb);
            ldx4(bfr + 12, b_addr[3] + kb);
#pragma unroll
            for (int im = 0; im < 2; im++)
#pragma unroll
                for (int in = 0; in < 8; in++)
                    mma16816(acc[im][in], afr[im], bfr[in * 2], bfr[in * 2 + 1]);
        }
        __syncthreads();
    }

    // epilogue: write fp32 + bias to g_gx
#pragma unroll
    for (int im = 0; im < 2; im++) {
#pragma unroll
        for (int h = 0; h < 2; h++) {
            int m = m0 + warp_m * 32 + im * 16 + h * 8 + (lane >> 2);
            int r = m & (MROWS - 1);
            int t = r >> 8, b = r & 255;
            float* gp = g_gx + (((size_t)cell * LL + t) * BB + b) * G4 + n0;
#pragma unroll
            for (int in = 0; in < 8; in++) {
                int col = warp_n * 64 + in * 8 + (lane & 3) * 2;
                float2 v;
                v.x = acc[im][in][2 * h + 0] + bias_s[col];
                v.y = acc[im][in][2 * h + 1] + bias_s[col + 1];
                *reinterpret_cast<float2*>(gp + col) = v;
            }
        }
    }
}

// ---------------------------------------------------------------------------
// Phase 2: recurrent LSTM, cluster of 2 CTAs per chain, weights in registers.
// ---------------------------------------------------------------------------
__global__ __launch_bounds__(256, 1) __cluster_dims__(2, 1, 1)
void k_recurrent(const float* __restrict__ Whh_h,
                 const float* __restrict__ Whh_f,
                 const float* __restrict__ Wffn)
{
    __shared__ float h_s[2][TB][HH];
    __shared__ float gates_s[256][TB + 1];
    __shared__ float c_s[TB][64];
    __shared__ float y_ws[TB][2];

    const int tid = threadIdx.x;
    uint32_t rank;
    asm("mov.u32 %0, %%cluster_ctarank;" : "=r"(rank));
    const int q    = blockIdx.x >> 1;
    const int cell = q >> 5;
    const int b0   = (q & 31) * TB;

    const float* W = cell ? Whh_f : Whh_h;

    const int rr = tid;
    const int g  = rr >> 6;
    const int jj = rr & 63;
    const int n  = g * HH + (int)rank * 64 + jj;

    unsigned long long w2[64];
    {
        const float2* wrow = reinterpret_cast<const float2*>(W + (size_t)n * HH);
#pragma unroll
        for (int i = 0; i < 64; i++) {
            float2 v = wrow[i];
            w2[i] = pack2(v.x, v.y);
        }
    }

    const int lane = tid & 31;
    const int wrp  = tid >> 5;
    const int jju  = tid & 63;
    const int bA   = tid >> 6;
    const float wf = Wffn[cell * HH + (int)rank * 64 + jju];
    const int jglob = (int)rank * 64 + jju;

    for (int i = tid; i < 2 * TB * HH; i += 256) (&h_s[0][0][0])[i] = 0.0f;
    for (int i = tid; i < TB * 64;     i += 256) (&c_s[0][0])[i]     = 0.0f;
    __syncthreads();
    asm volatile("barrier.cluster.arrive.aligned;" ::: "memory");
    asm volatile("barrier.cluster.wait.aligned;"   ::: "memory");

    const size_t cbase = (size_t)cell * LL * BB * G4 + (size_t)n;
    float gx[TB];
#pragma unroll
    for (int b = 0; b < TB; b++)
        gx[b] = g_gx[cbase + (size_t)(b0 + b) * G4];

    int buf = 0;
    for (int t = 0; t < LL; t++) {
        // prefetch next-step Gx
        float gxn[TB];
        {
            const float* gp = g_gx + cbase + ((size_t)(t + 1) * BB + b0) * G4;
#pragma unroll
            for (int b = 0; b < TB; b++)
                gxn[b] = (t + 1 < LL) ? gp[(size_t)b * G4] : 0.0f;
        }

        // matvec: gates[rr][b] = gx[b] + h[b] . w_row  (LDS.128 broadcast loads)
#pragma unroll
        for (int b = 0; b < TB; b++) {
            const longlong2* hp =
                reinterpret_cast<const longlong2*>(&h_s[buf][b][0]);
            unsigned long long a0 = 0ull, a1 = 0ull;
#pragma unroll
            for (int i = 0; i < 32; i++) {
                longlong2 v = hp[i];
                fma2(a0, (unsigned long long)v.x, w2[2 * i]);
                fma2(a1, (unsigned long long)v.y, w2[2 * i + 1]);
            }
            float2 s0 = unpack2(a0);
            float2 s1 = unpack2(a1);
            gates_s[rr][b] = gx[b] + ((s0.x + s0.y) + (s1.x + s1.y));
        }
        __syncthreads();

        // pointwise update: (jju, bA) and (jju, bA+4)
        const int nb = buf ^ 1;
        float yv[2];
#pragma unroll
        for (int u = 0; u < 2; u++) {
            const int b = bA + 4 * u;
            float ig = sigm(gates_s[jju][b]);
            float fg = sigm(gates_s[64 + jju][b]);
            float gg = tanha(gates_s[128 + jju][b]);
            float og = sigm(gates_s[192 + jju][b]);
            float c  = fg * c_s[b][jju] + ig * gg;
            c_s[b][jju] = c;
            float hv = og * tanha(c);
            h_s[nb][b][jglob] = hv;
            st_remote_f32(smem_u32(&h_s[nb][b][jglob]), rank ^ 1u, hv);
            yv[u] = hv * wf;
        }

        // publish arrivals early; hide cluster drain under y-reduction
        asm volatile("barrier.cluster.arrive.aligned;" ::: "memory");

#pragma unroll
        for (int u = 0; u < 2; u++) {
            float y = yv[u];
#pragma unroll
            for (int off = 16; off; off >>= 1)
                y += __shfl_xor_sync(0xffffffffu, y, off);
            if (lane == 0) y_ws[bA + 4 * u][wrp & 1] = y;
        }
        __syncthreads();

        if (tid < TB) {
            float y = y_ws[tid][0] + y_ws[tid][1];
            g_yp[((size_t)(cell * 2 + (int)rank) * BB + (b0 + tid)) * LL + t] = y;
        }

#pragma unroll
        for (int b = 0; b < TB; b++) gx[b] = gxn[b];
        buf ^= 1;

        asm volatile("barrier.cluster.wait.aligned;" ::: "memory");
    }
}

// ---------------------------------------------------------------------------
// Phase 3: out[b][t] = sum of 4 partials + b_ffn
// ---------------------------------------------------------------------------
__global__ void k_finalize(float* __restrict__ out, const float* __restrict__ bffn) {
    int i = blockIdx.x * 256 + threadIdx.x;
    if (i < BB * LL) {
        const size_t s = (size_t)BB * LL;
        out[i] = bffn[0] + g_yp[i] + g_yp[s + i] + g_yp[2 * s + i] + g_yp[3 * s + i];
    }
}

// ---------------------------------------------------------------------------
extern "C" void kernel_launch(void* const* d_in, const int* in_sizes, int n_in,
                              void* d_out, int out_size) {
    const float* hist  = (const float*)d_in[0];
    const float* fut   = (const float*)d_in[1];
    const float* Wih_h = (const float*)d_in[2];
    const float* Whh_h = (const float*)d_in[3];
    const float* bih_h = (const float*)d_in[4];
    const float* bhh_h = (const float*)d_in[5];
    const float* Wih_f = (const float*)d_in[6];
    const float* Whh_f = (const float*)d_in[7];
    const float* bih_f = (const float*)d_in[8];
    const float* bhh_f = (const float*)d_in[9];
    const float* Wffn  = (const float*)d_in[10];
    const float* bffn  = (const float*)d_in[11];
    float* out = (float*)d_out;

    k_convert<<<(2 * MROWS * 32) / 256, 256>>>(hist, fut);
    k_convert_w<<<(2 * G4 * 32) / 256, 256>>>(Wih_h, Wih_f);

    dim3 gg(G4 / 128, (2 * MROWS) / 128);   // (4, 2048)
    k_mma_gemm<<<gg, 256>>>(bih_h, bhh_h, bih_f, bhh_f);

    k_recurrent<<<128, 256>>>(Whh_h, Whh_f, Wffn);

    k_finalize<<<(BB * LL + 255) / 256, 256>>>(out, bffn);
}